// round 2
// baseline (speedup 1.0000x reference)
#include <cuda_runtime.h>
#include <cuda_bf16.h>
#include <math.h>

// Problem constants
#define HDIM   2880
#define NHEADS 64
#define NKV    8
#define DHEAD  64
#define GRP    8          // NHEADS / NKV
#define WIN    128
#define QKVW   5120       // (NHEADS + 2*NKV) * DHEAD
#define AOW    4096       // NHEADS * DHEAD
#define NMAX   1024

// Scratch (device globals: allocation-free)
__device__ float g_qkv[NMAX * QKVW];   // 20 MB
__device__ float g_attn[NMAX * AOW];   // 16 MB
__device__ int   g_positions[NMAX];

// ---------------------------------------------------------------------------
// Normalize positions: harness may deliver int32 or int64. Detect on-device
// (positions are monotonically increasing from 0 in this problem) and write
// canonical int32. int32-arange read as int64 gives p64[0] = 1<<32 != 0.
// ---------------------------------------------------------------------------
__global__ void norm_pos_kernel(const void* __restrict__ pos_raw, int n)
{
    const long long* p64 = (const long long*)pos_raw;
    const int*       p32 = (const int*)pos_raw;

    __shared__ int is64;
    if (threadIdx.x == 0) {
        long long v0 = p64[0];
        long long v1 = (n > 1) ? p64[1] : 1;
        is64 = (v0 == 0 && v1 == 1) ? 1 : 0;
    }
    __syncthreads();

    for (int i = threadIdx.x; i < n; i += blockDim.x)
        g_positions[i] = is64 ? (int)p64[i] : p32[i];
}

// ---------------------------------------------------------------------------
// SGEMM: C[M,N] = A[M,K] @ B[K,N], row-major, fp32.
// BM=128, BN=64, BK=8, 256 threads, 8x4 per-thread micro-tile.
// Requires: M % 128 == 0, N % 64 == 0, K % 8 == 0 (true for all our shapes).
// ---------------------------------------------------------------------------
#define BM 128
#define BN 64
#define BK 8

__global__ __launch_bounds__(256) void sgemm_kernel(
    const float* __restrict__ A, const float* __restrict__ B,
    float* __restrict__ C, int M, int N, int K)
{
    __shared__ float As[BK][BM];   // transposed A tile
    __shared__ float Bs[BK][BN];

    const int tid = threadIdx.x;
    const int m0 = blockIdx.y * BM;
    const int n0 = blockIdx.x * BN;

    const int arow = tid >> 1;             // 0..127
    const int acol = (tid & 1) << 2;       // 0 or 4
    const int brow = tid >> 5;             // 0..7
    const int bcol = (tid & 31) << 1;      // 0..62

    const float* Aptr = A + (size_t)(m0 + arow) * K + acol;
    const float* Bptr = B + (size_t)brow * N + n0 + bcol;

    float4 a_reg = *(const float4*)Aptr;
    float2 b_reg = *(const float2*)Bptr;

    const int tx = tid & 15;   // col group: 4 cols at tx*4
    const int ty = tid >> 4;   // row group: 8 rows at ty*8

    float acc[8][4];
    #pragma unroll
    for (int i = 0; i < 8; i++)
        #pragma unroll
        for (int j = 0; j < 4; j++) acc[i][j] = 0.0f;

    const int ktiles = K / BK;
    for (int kt = 0; kt < ktiles; kt++) {
        As[acol + 0][arow] = a_reg.x;
        As[acol + 1][arow] = a_reg.y;
        As[acol + 2][arow] = a_reg.z;
        As[acol + 3][arow] = a_reg.w;
        *(float2*)&Bs[brow][bcol] = b_reg;
        __syncthreads();

        if (kt + 1 < ktiles) {
            a_reg = *(const float4*)(Aptr + (size_t)(kt + 1) * BK);
            b_reg = *(const float2*)(Bptr + (size_t)(kt + 1) * BK * N);
        }

        #pragma unroll
        for (int kk = 0; kk < BK; kk++) {
            float a[8], b[4];
            *(float4*)&a[0] = *(const float4*)&As[kk][ty * 8];
            *(float4*)&a[4] = *(const float4*)&As[kk][ty * 8 + 4];
            *(float4*)&b[0] = *(const float4*)&Bs[kk][tx * 4];
            #pragma unroll
            for (int i = 0; i < 8; i++)
                #pragma unroll
                for (int j = 0; j < 4; j++)
                    acc[i][j] += a[i] * b[j];
        }
        __syncthreads();
    }

    float* Cptr = C + (size_t)(m0 + ty * 8) * N + n0 + tx * 4;
    #pragma unroll
    for (int i = 0; i < 8; i++)
        *(float4*)(Cptr + (size_t)i * N) = *(float4*)&acc[i][0];
}

// ---------------------------------------------------------------------------
// RoPE in-place on qkv (q: 64 heads, k: 8 heads). One thread per (tok, head, j).
// ---------------------------------------------------------------------------
__global__ void rope_kernel(float* __restrict__ qkv, int n)
{
    int idx = blockIdx.x * blockDim.x + threadIdx.x;
    int total = n * (NHEADS + NKV) * (DHEAD / 2);
    if (idx >= total) return;

    int j   = idx & 31;
    int h   = (idx >> 5) % (NHEADS + NKV);
    int tok = idx / ((NHEADS + NKV) * 32);

    float* base;
    if (h < NHEADS)
        base = qkv + (size_t)tok * QKVW + h * DHEAD;
    else
        base = qkv + (size_t)tok * QKVW + NHEADS * DHEAD + (h - NHEADS) * DHEAD;

    float pos = (float)g_positions[tok];
    float inv_freq = powf(150000.0f, -((float)j) / 32.0f);
    float ang = pos * inv_freq;
    float s, c;
    sincosf(ang, &s, &c);

    float x1 = base[j];
    float x2 = base[j + 32];
    base[j]      = x1 * c - x2 * s;
    base[j + 32] = x2 * c + x1 * s;
}

// ---------------------------------------------------------------------------
// Sliding-window attention with sinks. Grid: (n, NKV). Block: 128 threads.
// ---------------------------------------------------------------------------
__global__ __launch_bounds__(128) void attn_kernel(
    const float* __restrict__ qkv, const float* __restrict__ sinks,
    float* __restrict__ attn_out, int n)
{
    __shared__ float kbuf[WIN][DHEAD + 1];   // reused for V
    __shared__ float qs[GRP][DHEAD];         // scaled q
    __shared__ float sc[GRP][WIN];           // softmax probs
    __shared__ float red[GRP][4];
    __shared__ float mfin[GRP];
    __shared__ float dinv[GRP];

    const int tok = blockIdx.x;
    const int kv  = blockIdx.y;
    const int tid = threadIdx.x;
    const int lane = tid & 31;
    const int wrp  = tid >> 5;

    const int pos = g_positions[tok];

    // load q for this kv group's 8 heads (contiguous 512 floats), pre-scaled
    {
        const float* qbase = qkv + (size_t)tok * QKVW + (size_t)kv * GRP * DHEAD;
        for (int i = tid; i < GRP * DHEAD; i += 128)
            qs[i >> 6][i & 63] = qbase[i] * 0.125f;   // 1/sqrt(64)
    }

    // load K window: row w <-> token (pos - 127 + w), clipped
    for (int i = tid; i < WIN * (DHEAD / 4); i += 128) {
        int w  = i >> 4;
        int c4 = (i & 15) << 2;
        int t = pos - (WIN - 1) + w;
        t = max(0, min(t, n - 1));
        float4 kd = *(const float4*)(qkv + (size_t)t * QKVW + NHEADS * DHEAD
                                     + (size_t)kv * DHEAD + c4);
        kbuf[w][c4]     = kd.x;
        kbuf[w][c4 + 1] = kd.y;
        kbuf[w][c4 + 2] = kd.z;
        kbuf[w][c4 + 3] = kd.w;
    }
    __syncthreads();

    // scores: this thread owns window slot w = tid
    float s[GRP];
    #pragma unroll
    for (int g = 0; g < GRP; g++) s[g] = 0.0f;
    #pragma unroll 4
    for (int d = 0; d < DHEAD; d++) {
        float kd = kbuf[tid][d];
        #pragma unroll
        for (int g = 0; g < GRP; g++) s[g] += kd * qs[g][d];
    }
    const bool valid = (pos - (WIN - 1) + tid) >= 0;
    if (!valid) {
        #pragma unroll
        for (int g = 0; g < GRP; g++) s[g] = -INFINITY;
    }

    // max reduce per group
    #pragma unroll
    for (int g = 0; g < GRP; g++) {
        float v = s[g];
        #pragma unroll
        for (int off = 16; off; off >>= 1)
            v = fmaxf(v, __shfl_xor_sync(0xffffffffu, v, off));
        if (lane == 0) red[g][wrp] = v;
    }
    __syncthreads();
    if (tid < GRP) {
        float m = fmaxf(fmaxf(red[tid][0], red[tid][1]),
                        fmaxf(red[tid][2], red[tid][3]));
        m = fmaxf(m, sinks[kv * GRP + tid]);
        mfin[tid] = m;
    }
    __syncthreads();

    // probs + sum reduce per group
    #pragma unroll
    for (int g = 0; g < GRP; g++) {
        float p = valid ? expf(s[g] - mfin[g]) : 0.0f;
        sc[g][tid] = p;
        float v = p;
        #pragma unroll
        for (int off = 16; off; off >>= 1)
            v += __shfl_xor_sync(0xffffffffu, v, off);
        if (lane == 0) red[g][wrp] = v;
    }
    __syncthreads();
    if (tid < GRP) {
        float d = red[tid][0] + red[tid][1] + red[tid][2] + red[tid][3];
        d += expf(sinks[kv * GRP + tid] - mfin[tid]);
        dinv[tid] = 1.0f / d;
    }
    __syncthreads();

    // load V window into kbuf (reuse)
    for (int i = tid; i < WIN * (DHEAD / 4); i += 128) {
        int w  = i >> 4;
        int c4 = (i & 15) << 2;
        int t = pos - (WIN - 1) + w;
        t = max(0, min(t, n - 1));
        float4 vd = *(const float4*)(qkv + (size_t)t * QKVW
                                     + (NHEADS + NKV) * DHEAD
                                     + (size_t)kv * DHEAD + c4);
        kbuf[w][c4]     = vd.x;
        kbuf[w][c4 + 1] = vd.y;
        kbuf[w][c4 + 2] = vd.z;
        kbuf[w][c4 + 3] = vd.w;
    }
    __syncthreads();

    // output: thread owns (4 groups) x (1 dim)
    {
        const int d  = tid & 63;
        const int g0 = (tid >> 6) * 4;
        float acc0 = 0.f, acc1 = 0.f, acc2 = 0.f, acc3 = 0.f;
        #pragma unroll 4
        for (int w = 0; w < WIN; w++) {
            float vd = kbuf[w][d];
            acc0 += sc[g0 + 0][w] * vd;
            acc1 += sc[g0 + 1][w] * vd;
            acc2 += sc[g0 + 2][w] * vd;
            acc3 += sc[g0 + 3][w] * vd;
        }
        float* ob = attn_out + (size_t)tok * AOW + ((size_t)kv * GRP + g0) * DHEAD + d;
        ob[0 * DHEAD] = acc0 * dinv[g0 + 0];
        ob[1 * DHEAD] = acc1 * dinv[g0 + 1];
        ob[2 * DHEAD] = acc2 * dinv[g0 + 2];
        ob[3 * DHEAD] = acc3 * dinv[g0 + 3];
    }
}

// ---------------------------------------------------------------------------
extern "C" void kernel_launch(void* const* d_in, const int* in_sizes, int n_in,
                              void* d_out, int out_size)
{
    const float* hs    = (const float*)d_in[0];
    const float* wqkv  = (const float*)d_in[1];
    const float* wo    = (const float*)d_in[2];
    const float* sinks = (const float*)d_in[3];
    const void*  pos   = (const void*)d_in[4];
    float*       out   = (float*)d_out;

    const int n = in_sizes[0] / HDIM;   // 1024

    float* qkv_ptr  = nullptr;
    float* attn_ptr = nullptr;
    cudaGetSymbolAddress((void**)&qkv_ptr,  g_qkv);
    cudaGetSymbolAddress((void**)&attn_ptr, g_attn);

    // 0) normalize positions (int32 vs int64 robust)
    norm_pos_kernel<<<1, 1024>>>(pos, n);

    // 1) qkv = hs @ Wqkv
    {
        dim3 grid(QKVW / BN, n / BM);
        sgemm_kernel<<<grid, 256>>>(hs, wqkv, qkv_ptr, n, QKVW, HDIM);
    }
    // 2) RoPE in place on q and k
    {
        int total = n * (NHEADS + NKV) * (DHEAD / 2);
        rope_kernel<<<(total + 255) / 256, 256>>>(qkv_ptr, n);
    }
    // 3) sliding-window attention with sinks
    {
        dim3 grid(n, NKV);
        attn_kernel<<<grid, 128>>>(qkv_ptr, sinks, attn_ptr, n);
    }
    // 4) out = attn @ Wo
    {
        dim3 grid(HDIM / BN, n / BM);
        sgemm_kernel<<<grid, 256>>>(attn_ptr, wo, out, n, HDIM, AOW);
    }
}

// round 3
// speedup vs baseline: 1.9033x; 1.9033x over previous
#include <cuda_runtime.h>
#include <cuda_bf16.h>
#include <math.h>
#include <stdint.h>

// Problem constants
#define HDIM   2880
#define NHEADS 64
#define NKV    8
#define DHEAD  64
#define GRP    8          // NHEADS / NKV
#define WIN    128
#define QKVW   5120       // (NHEADS + 2*NKV) * DHEAD
#define AOW    4096       // NHEADS * DHEAD
#define NMAX   1024

// Scratch (device globals: allocation-free)
__device__ float g_qkv[NMAX * QKVW];   // 20 MB
__device__ float g_attn[NMAX * AOW];   // 16 MB
__device__ int   g_positions[NMAX];

__device__ __align__(16) __nv_bfloat16 g_ahi[NMAX * HDIM];
__device__ __align__(16) __nv_bfloat16 g_alo[NMAX * HDIM];
__device__ __align__(16) __nv_bfloat16 g_athi[NMAX * AOW];
__device__ __align__(16) __nv_bfloat16 g_atlo[NMAX * AOW];
__device__ __align__(16) __nv_bfloat16 g_wqh[HDIM * QKVW];
__device__ __align__(16) __nv_bfloat16 g_wql[HDIM * QKVW];
__device__ __align__(16) __nv_bfloat16 g_woh[AOW * HDIM];
__device__ __align__(16) __nv_bfloat16 g_wol[AOW * HDIM];

// ---------------------------------------------------------------------------
// positions normalizer (int32 vs int64 robust; positions are arange here)
// ---------------------------------------------------------------------------
__global__ void norm_pos_kernel(const void* __restrict__ pos_raw, int n)
{
    const long long* p64 = (const long long*)pos_raw;
    const int*       p32 = (const int*)pos_raw;
    __shared__ int is64;
    if (threadIdx.x == 0) {
        long long v0 = p64[0];
        long long v1 = (n > 1) ? p64[1] : 1;
        is64 = (v0 == 0 && v1 == 1) ? 1 : 0;
    }
    __syncthreads();
    for (int i = threadIdx.x; i < n; i += blockDim.x)
        g_positions[i] = is64 ? (int)p64[i] : p32[i];
}

// ---------------------------------------------------------------------------
// fp32 -> bf16 hi/lo split (vectorized x4)
// ---------------------------------------------------------------------------
__global__ void split_kernel(const float* __restrict__ src,
                             __nv_bfloat16* __restrict__ hi,
                             __nv_bfloat16* __restrict__ lo, int n4)
{
    int i = blockIdx.x * blockDim.x + threadIdx.x;
    if (i >= n4) return;
    float4 v = ((const float4*)src)[i];

    __nv_bfloat16 h0 = __float2bfloat16(v.x);
    __nv_bfloat16 h1 = __float2bfloat16(v.y);
    __nv_bfloat16 h2 = __float2bfloat16(v.z);
    __nv_bfloat16 h3 = __float2bfloat16(v.w);
    __nv_bfloat16 l0 = __float2bfloat16(v.x - __bfloat162float(h0));
    __nv_bfloat16 l1 = __float2bfloat16(v.y - __bfloat162float(h1));
    __nv_bfloat16 l2 = __float2bfloat16(v.z - __bfloat162float(h2));
    __nv_bfloat16 l3 = __float2bfloat16(v.w - __bfloat162float(h3));

    __nv_bfloat162 hp0 = __nv_bfloat162(h0, h1);
    __nv_bfloat162 hp1 = __nv_bfloat162(h2, h3);
    __nv_bfloat162 lp0 = __nv_bfloat162(l0, l1);
    __nv_bfloat162 lp1 = __nv_bfloat162(l2, l3);

    uint2 hv, lv;
    hv.x = *(uint32_t*)&hp0; hv.y = *(uint32_t*)&hp1;
    lv.x = *(uint32_t*)&lp0; lv.y = *(uint32_t*)&lp1;
    ((uint2*)hi)[i] = hv;
    ((uint2*)lo)[i] = lv;
}

// ---------------------------------------------------------------------------
// MMA helpers
// ---------------------------------------------------------------------------
__device__ __forceinline__ uint32_t smem_u32(const void* p) {
    return (uint32_t)__cvta_generic_to_shared(p);
}
__device__ __forceinline__ void ldsm_x4(uint32_t* r, uint32_t addr) {
    asm volatile("ldmatrix.sync.aligned.m8n8.x4.shared.b16 {%0,%1,%2,%3}, [%4];"
        : "=r"(r[0]), "=r"(r[1]), "=r"(r[2]), "=r"(r[3]) : "r"(addr));
}
__device__ __forceinline__ void ldsm_x4_t(uint32_t* r, uint32_t addr) {
    asm volatile("ldmatrix.sync.aligned.m8n8.x4.trans.shared.b16 {%0,%1,%2,%3}, [%4];"
        : "=r"(r[0]), "=r"(r[1]), "=r"(r[2]), "=r"(r[3]) : "r"(addr));
}
__device__ __forceinline__ void mma_bf16(float* d, const uint32_t* a, const uint32_t* b) {
    asm volatile(
        "mma.sync.aligned.m16n8k16.row.col.f32.bf16.bf16.f32 "
        "{%0,%1,%2,%3}, {%4,%5,%6,%7}, {%8,%9}, {%0,%1,%2,%3};"
        : "+f"(d[0]), "+f"(d[1]), "+f"(d[2]), "+f"(d[3])
        : "r"(a[0]), "r"(a[1]), "r"(a[2]), "r"(a[3]), "r"(b[0]), "r"(b[1]));
}

// ---------------------------------------------------------------------------
// 3-pass split-bf16 GEMM: C[M,N] (fp32) = (Ahi+Alo)(Bhi+Blo) - Alo*Blo
// Block tile 128x64x32, 256 threads (8 warps of 32x32 warp tiles).
// Requires M%128==0, N%64==0, K%32==0 (true: M=1024, N in {5120,2880},
// K in {2880,4096}).
// ---------------------------------------------------------------------------
#define GBM 128
#define GBN 64
#define GBK 32
#define SKA 56   // A smem row stride (halves): 112B -> conflict-free ldmatrix
#define SKB 72   // B smem row stride (halves): 144B -> conflict-free ldmatrix

__global__ __launch_bounds__(256, 2) void gemm3_kernel(
    const __nv_bfloat16* __restrict__ Ahi, const __nv_bfloat16* __restrict__ Alo,
    const __nv_bfloat16* __restrict__ Bhi, const __nv_bfloat16* __restrict__ Blo,
    float* __restrict__ C, int M, int N, int K)
{
    __shared__ __align__(16) __nv_bfloat16 sAhi[GBM * SKA];
    __shared__ __align__(16) __nv_bfloat16 sAlo[GBM * SKA];
    __shared__ __align__(16) __nv_bfloat16 sBhi[GBK * SKB];
    __shared__ __align__(16) __nv_bfloat16 sBlo[GBK * SKB];

    const int tid  = threadIdx.x;
    const int wid  = tid >> 5;
    const int lane = tid & 31;
    const int m0 = blockIdx.y * GBM;
    const int n0 = blockIdx.x * GBN;

    const int wm = (wid & 3) * 32;   // warp row offset in tile
    const int wn = (wid >> 2) * 32;  // warp col offset in tile

    // global load mapping
    const int a_r = tid >> 2;          // 0..63
    const int a_c = (tid & 3) * 8;     // halves within BK
    const int b_r = tid >> 3;          // 0..31
    const int b_c = (tid & 7) * 8;     // halves within BN

    const __nv_bfloat16* pAhi = Ahi + (size_t)(m0 + a_r) * K + a_c;
    const __nv_bfloat16* pAlo = Alo + (size_t)(m0 + a_r) * K + a_c;
    const __nv_bfloat16* pBhi = Bhi + (size_t)b_r * N + n0 + b_c;
    const __nv_bfloat16* pBlo = Blo + (size_t)b_r * N + n0 + b_c;

    uint4 rAh0 = *(const uint4*)pAhi;
    uint4 rAh1 = *(const uint4*)(pAhi + (size_t)64 * K);
    uint4 rAl0 = *(const uint4*)pAlo;
    uint4 rAl1 = *(const uint4*)(pAlo + (size_t)64 * K);
    uint4 rBh  = *(const uint4*)pBhi;
    uint4 rBl  = *(const uint4*)pBlo;

    float acc[2][4][4];
    #pragma unroll
    for (int i = 0; i < 2; i++)
        #pragma unroll
        for (int j = 0; j < 4; j++)
            #pragma unroll
            for (int k = 0; k < 4; k++) acc[i][j][k] = 0.0f;

    // smem store offsets (halves)
    const int sa_off0 = a_r * SKA + a_c;
    const int sa_off1 = (a_r + 64) * SKA + a_c;
    const int sb_off  = b_r * SKB + b_c;

    // ldmatrix source addresses (bytes), constant parts
    const int lm_row = lane & 15;            // row within 16-row group
    const int lm_kch = (lane >> 4) * 8;      // k chunk (halves)
    const uint32_t sAhi_b = smem_u32(sAhi);
    const uint32_t sAlo_b = smem_u32(sAlo);
    const uint32_t sBhi_b = smem_u32(sBhi);
    const uint32_t sBlo_b = smem_u32(sBlo);

    const int ktiles = K / GBK;
    for (int kt = 0; kt < ktiles; kt++) {
        *(uint4*)&sAhi[sa_off0] = rAh0;
        *(uint4*)&sAhi[sa_off1] = rAh1;
        *(uint4*)&sAlo[sa_off0] = rAl0;
        *(uint4*)&sAlo[sa_off1] = rAl1;
        *(uint4*)&sBhi[sb_off]  = rBh;
        *(uint4*)&sBlo[sb_off]  = rBl;
        __syncthreads();

        if (kt + 1 < ktiles) {
            pAhi += GBK; pAlo += GBK;
            pBhi += (size_t)GBK * N; pBlo += (size_t)GBK * N;
            rAh0 = *(const uint4*)pAhi;
            rAh1 = *(const uint4*)(pAhi + (size_t)64 * K);
            rAl0 = *(const uint4*)pAlo;
            rAl1 = *(const uint4*)(pAlo + (size_t)64 * K);
            rBh  = *(const uint4*)pBhi;
            rBl  = *(const uint4*)pBlo;
        }

        #pragma unroll
        for (int ks = 0; ks < 2; ks++) {
            const int k0 = ks * 16;

            uint32_t ah[2][4], al[2][4], bh[2][4], bl[2][4];
            #pragma unroll
            for (int mi = 0; mi < 2; mi++) {
                uint32_t off = (uint32_t)((wm + mi * 16 + lm_row) * SKA + k0 + lm_kch) * 2;
                ldsm_x4(ah[mi], sAhi_b + off);
                ldsm_x4(al[mi], sAlo_b + off);
            }
            #pragma unroll
            for (int np = 0; np < 2; np++) {
                // rows = k, col chunk covers 16 cols (two n8 tiles)
                uint32_t off = (uint32_t)((k0 + lm_row) * SKB + wn + np * 16 + lm_kch) * 2;
                ldsm_x4_t(bh[np], sBhi_b + off);
                ldsm_x4_t(bl[np], sBlo_b + off);
            }

            #pragma unroll
            for (int mi = 0; mi < 2; mi++) {
                #pragma unroll
                for (int nj = 0; nj < 4; nj++) {
                    const uint32_t* bhp = &bh[nj >> 1][(nj & 1) * 2];
                    const uint32_t* blp = &bl[nj >> 1][(nj & 1) * 2];
                    mma_bf16(acc[mi][nj], ah[mi], bhp);   // hi*hi
                    mma_bf16(acc[mi][nj], ah[mi], blp);   // hi*lo
                    mma_bf16(acc[mi][nj], al[mi], bhp);   // lo*hi
                }
            }
        }
        __syncthreads();
    }

    // epilogue
    const int er = lane >> 2;
    const int ec = (lane & 3) * 2;
    #pragma unroll
    for (int mi = 0; mi < 2; mi++) {
        #pragma unroll
        for (int nj = 0; nj < 4; nj++) {
            const int row = m0 + wm + mi * 16 + er;
            const int col = n0 + wn + nj * 8 + ec;
            float2 v01; v01.x = acc[mi][nj][0]; v01.y = acc[mi][nj][1];
            float2 v23; v23.x = acc[mi][nj][2]; v23.y = acc[mi][nj][3];
            *(float2*)&C[(size_t)row * N + col]       = v01;
            *(float2*)&C[(size_t)(row + 8) * N + col] = v23;
        }
    }
}

// ---------------------------------------------------------------------------
// RoPE in-place on qkv (q: 64 heads, k: 8 heads).
// ---------------------------------------------------------------------------
__global__ void rope_kernel(float* __restrict__ qkv, int n)
{
    int idx = blockIdx.x * blockDim.x + threadIdx.x;
    int total = n * (NHEADS + NKV) * (DHEAD / 2);
    if (idx >= total) return;

    int j   = idx & 31;
    int h   = (idx >> 5) % (NHEADS + NKV);
    int tok = idx / ((NHEADS + NKV) * 32);

    float* base;
    if (h < NHEADS)
        base = qkv + (size_t)tok * QKVW + h * DHEAD;
    else
        base = qkv + (size_t)tok * QKVW + NHEADS * DHEAD + (h - NHEADS) * DHEAD;

    float pos = (float)g_positions[tok];
    float inv_freq = powf(150000.0f, -((float)j) / 32.0f);
    float ang = pos * inv_freq;
    float s, c;
    sincosf(ang, &s, &c);

    float x1 = base[j];
    float x2 = base[j + 32];
    base[j]      = x1 * c - x2 * s;
    base[j + 32] = x2 * c + x1 * s;
}

// ---------------------------------------------------------------------------
// Sliding-window attention with sinks. Grid: (n, NKV). Block: 128 threads.
// ---------------------------------------------------------------------------
__global__ __launch_bounds__(128) void attn_kernel(
    const float* __restrict__ qkv, const float* __restrict__ sinks,
    float* __restrict__ attn_out, int n)
{
    __shared__ float kbuf[WIN][DHEAD + 1];   // reused for V
    __shared__ float qs[GRP][DHEAD];
    __shared__ float sc[GRP][WIN];
    __shared__ float red[GRP][4];
    __shared__ float mfin[GRP];
    __shared__ float dinv[GRP];

    const int tok = blockIdx.x;
    const int kv  = blockIdx.y;
    const int tid = threadIdx.x;
    const int lane = tid & 31;
    const int wrp  = tid >> 5;

    const int pos = g_positions[tok];

    {
        const float* qbase = qkv + (size_t)tok * QKVW + (size_t)kv * GRP * DHEAD;
        for (int i = tid; i < GRP * DHEAD; i += 128)
            qs[i >> 6][i & 63] = qbase[i] * 0.125f;
    }

    for (int i = tid; i < WIN * (DHEAD / 4); i += 128) {
        int w  = i >> 4;
        int c4 = (i & 15) << 2;
        int t = pos - (WIN - 1) + w;
        t = max(0, min(t, n - 1));
        float4 kd = *(const float4*)(qkv + (size_t)t * QKVW + NHEADS * DHEAD
                                     + (size_t)kv * DHEAD + c4);
        kbuf[w][c4]     = kd.x;
        kbuf[w][c4 + 1] = kd.y;
        kbuf[w][c4 + 2] = kd.z;
        kbuf[w][c4 + 3] = kd.w;
    }
    __syncthreads();

    float s[GRP];
    #pragma unroll
    for (int g = 0; g < GRP; g++) s[g] = 0.0f;
    #pragma unroll 4
    for (int d = 0; d < DHEAD; d++) {
        float kd = kbuf[tid][d];
        #pragma unroll
        for (int g = 0; g < GRP; g++) s[g] += kd * qs[g][d];
    }
    const bool valid = (pos - (WIN - 1) + tid) >= 0;
    if (!valid) {
        #pragma unroll
        for (int g = 0; g < GRP; g++) s[g] = -INFINITY;
    }

    #pragma unroll
    for (int g = 0; g < GRP; g++) {
        float v = s[g];
        #pragma unroll
        for (int off = 16; off; off >>= 1)
            v = fmaxf(v, __shfl_xor_sync(0xffffffffu, v, off));
        if (lane == 0) red[g][wrp] = v;
    }
    __syncthreads();
    if (tid < GRP) {
        float m = fmaxf(fmaxf(red[tid][0], red[tid][1]),
                        fmaxf(red[tid][2], red[tid][3]));
        m = fmaxf(m, sinks[kv * GRP + tid]);
        mfin[tid] = m;
    }
    __syncthreads();

    #pragma unroll
    for (int g = 0; g < GRP; g++) {
        float p = valid ? expf(s[g] - mfin[g]) : 0.0f;
        sc[g][tid] = p;
        float v = p;
        #pragma unroll
        for (int off = 16; off; off >>= 1)
            v += __shfl_xor_sync(0xffffffffu, v, off);
        if (lane == 0) red[g][wrp] = v;
    }
    __syncthreads();
    if (tid < GRP) {
        float d = red[tid][0] + red[tid][1] + red[tid][2] + red[tid][3];
        d += expf(sinks[kv * GRP + tid] - mfin[tid]);
        dinv[tid] = 1.0f / d;
    }
    __syncthreads();

    for (int i = tid; i < WIN * (DHEAD / 4); i += 128) {
        int w  = i >> 4;
        int c4 = (i & 15) << 2;
        int t = pos - (WIN - 1) + w;
        t = max(0, min(t, n - 1));
        float4 vd = *(const float4*)(qkv + (size_t)t * QKVW
                                     + (NHEADS + NKV) * DHEAD
                                     + (size_t)kv * DHEAD + c4);
        kbuf[w][c4]     = vd.x;
        kbuf[w][c4 + 1] = vd.y;
        kbuf[w][c4 + 2] = vd.z;
        kbuf[w][c4 + 3] = vd.w;
    }
    __syncthreads();

    {
        const int d  = tid & 63;
        const int g0 = (tid >> 6) * 4;
        float acc0 = 0.f, acc1 = 0.f, acc2 = 0.f, acc3 = 0.f;
        #pragma unroll 4
        for (int w = 0; w < WIN; w++) {
            float vd = kbuf[w][d];
            acc0 += sc[g0 + 0][w] * vd;
            acc1 += sc[g0 + 1][w] * vd;
            acc2 += sc[g0 + 2][w] * vd;
            acc3 += sc[g0 + 3][w] * vd;
        }
        float* ob = attn_out + (size_t)tok * AOW + ((size_t)kv * GRP + g0) * DHEAD + d;
        ob[0 * DHEAD] = acc0 * dinv[g0 + 0];
        ob[1 * DHEAD] = acc1 * dinv[g0 + 1];
        ob[2 * DHEAD] = acc2 * dinv[g0 + 2];
        ob[3 * DHEAD] = acc3 * dinv[g0 + 3];
    }
}

// ---------------------------------------------------------------------------
extern "C" void kernel_launch(void* const* d_in, const int* in_sizes, int n_in,
                              void* d_out, int out_size)
{
    const float* hs    = (const float*)d_in[0];
    const float* wqkv  = (const float*)d_in[1];
    const float* wo    = (const float*)d_in[2];
    const float* sinks = (const float*)d_in[3];
    const void*  pos   = (const void*)d_in[4];
    float*       out   = (float*)d_out;

    const int n = in_sizes[0] / HDIM;   // 1024

    float *qkv_ptr, *attn_ptr;
    __nv_bfloat16 *ahi, *alo, *athi, *atlo, *wqh, *wql, *woh, *wol;
    cudaGetSymbolAddress((void**)&qkv_ptr,  g_qkv);
    cudaGetSymbolAddress((void**)&attn_ptr, g_attn);
    cudaGetSymbolAddress((void**)&ahi,  g_ahi);
    cudaGetSymbolAddress((void**)&alo,  g_alo);
    cudaGetSymbolAddress((void**)&athi, g_athi);
    cudaGetSymbolAddress((void**)&atlo, g_atlo);
    cudaGetSymbolAddress((void**)&wqh,  g_wqh);
    cudaGetSymbolAddress((void**)&wql,  g_wql);
    cudaGetSymbolAddress((void**)&woh,  g_woh);
    cudaGetSymbolAddress((void**)&wol,  g_wol);

    // 0) normalize positions
    norm_pos_kernel<<<1, 1024>>>(pos, n);

    // 1) bf16 hi/lo splits
    {
        int n4 = (n * HDIM) / 4;
        split_kernel<<<(n4 + 255) / 256, 256>>>(hs, ahi, alo, n4);
        n4 = (HDIM * QKVW) / 4;
        split_kernel<<<(n4 + 255) / 256, 256>>>(wqkv, wqh, wql, n4);
        n4 = (AOW * HDIM) / 4;
        split_kernel<<<(n4 + 255) / 256, 256>>>(wo, woh, wol, n4);
    }

    // 2) qkv = hs @ Wqkv  (tensor core, 3-pass split-bf16)
    {
        dim3 grid(QKVW / GBN, n / GBM);
        gemm3_kernel<<<grid, 256>>>(ahi, alo, wqh, wql, qkv_ptr, n, QKVW, HDIM);
    }

    // 3) RoPE in place on q and k
    {
        int total = n * (NHEADS + NKV) * (DHEAD / 2);
        rope_kernel<<<(total + 255) / 256, 256>>>(qkv_ptr, n);
    }

    // 4) sliding-window attention with sinks
    {
        dim3 grid(n, NKV);
        attn_kernel<<<grid, 128>>>(qkv_ptr, sinks, attn_ptr, n);
    }

    // 5) split attention output, then out = attn @ Wo
    {
        int n4 = (n * AOW) / 4;
        split_kernel<<<(n4 + 255) / 256, 256>>>(attn_ptr, athi, atlo, n4);
        dim3 grid(HDIM / GBN, n / GBM);
        gemm3_kernel<<<grid, 256>>>(athi, atlo, woh, wol, out, n, HDIM, AOW);
    }
}